// round 6
// baseline (speedup 1.0000x reference)
#include <cuda_runtime.h>
#include <cuda_fp16.h>
#include <cstdint>

// out[b,s,t] = sum_k x[b, t+k-271] * W[s,k];  B=128, T=4096, S=64, K=543.
// fp16 mma.sync.m16n8k16 implicit GEMM, single pass, fp32 accumulate.
// Scale-adaptive k-range skip: Ricker support ~6 sigma per scale tile.

#define T_DIM   4096
#define S_DIM   64
#define K_DIM   543
#define NSTEP   34       // k16 steps over KPAD=544
#define WROW    552      // padded W row (conflict-free b-frag LDS)
#define TT      128      // t tile (M)
#define WIN     672      // x window: TT + 544
#define XROW    688      // padded x copy row (elems)

#define WS_BYTES   (64 * WROW * 2)                 // 70656
#define X_OFF      WS_BYTES
#define SMEM_BYTES (WS_BYTES + 2 * XROW * 2)       // 73408

__device__ uint16_t g_W[64][WROW];     // fp16, zero-padded

__global__ void prep_bank(const float* __restrict__ W) {
    int idx = blockIdx.x * blockDim.x + threadIdx.x;
    if (idx >= 64 * WROW) return;
    int s  = idx / WROW;
    int kk = idx % WROW;
    float w = (kk < K_DIM) ? W[s * K_DIM + kk] : 0.0f;
    __half h = __float2half_rn(w);
    g_W[s][kk] = *reinterpret_cast<uint16_t*>(&h);
}

__device__ __forceinline__ uint32_t smem_u32(const void* p) {
    uint32_t a;
    asm("{ .reg .u64 t; cvta.to.shared.u64 t, %1; cvt.u32.u64 %0, t; }" : "=r"(a) : "l"(p));
    return a;
}
__device__ __forceinline__ uint32_t lds32(uint32_t a) {
    uint32_t v; asm volatile("ld.shared.b32 %0, [%1];" : "=r"(v) : "r"(a)); return v;
}
__device__ __forceinline__ void mma16816(float* c, uint32_t a0, uint32_t a1,
                                         uint32_t a2, uint32_t a3,
                                         uint32_t b0, uint32_t b1) {
    asm volatile(
        "mma.sync.aligned.m16n8k16.row.col.f32.f16.f16.f32 "
        "{%0,%1,%2,%3}, {%4,%5,%6,%7}, {%8,%9}, {%0,%1,%2,%3};"
        : "+f"(c[0]), "+f"(c[1]), "+f"(c[2]), "+f"(c[3])
        : "r"(a0), "r"(a1), "r"(a2), "r"(a3), "r"(b0), "r"(b1));
}

extern __shared__ char smem_raw[];

__global__ __launch_bounds__(256, 3)
void cwt_mma_kernel(const float* __restrict__ x, float* __restrict__ out) {
    uint16_t* Wsm  = reinterpret_cast<uint16_t*>(smem_raw);
    uint16_t* Xsm  = reinterpret_cast<uint16_t*>(smem_raw + X_OFF);
    float*    Obuf = reinterpret_cast<float*>(smem_raw);   // epilogue reuse

    const int tid  = threadIdx.x;
    const int wid  = tid >> 5;
    const int lane = tid & 31;
    const int t0   = blockIdx.x * TT;
    const int b    = blockIdx.y;

    // ---- stage W (entire padded bank, fp16) ----
    {
        const int4* src = reinterpret_cast<const int4*>(&g_W[0][0]);
        int4* dst = reinterpret_cast<int4*>(Wsm);
        for (int i = tid; i < WS_BYTES / 16; i += 256) dst[i] = src[i];
    }
    // ---- stage x window (fp16 + 1-elem-shifted copy) ----
    {
        const float* xr = x + (size_t)b * T_DIM;
        for (int i = tid; i < WIN; i += 256) {
            int g = t0 + i - 271;
            float v = (g >= 0 && g < T_DIM) ? xr[g] : 0.0f;
            __half h = __float2half_rn(v);
            uint16_t hb = *reinterpret_cast<uint16_t*>(&h);
            Xsm[i] = hb;
            if (i) Xsm[XROW + i - 1] = hb;
        }
    }
    __syncthreads();

    // ---- fragment addresses ----
    const int g    = lane >> 2;
    const int q    = lane & 3;
    const int podd = g & 1;
    const int eb   = 16 * wid + g + 2 * q - podd;
    const uint32_t xa  = smem_u32(Xsm) + (uint32_t)((podd * XROW + eb) * 2);
    const uint32_t wb0 = smem_u32(Wsm) + (uint32_t)((g * WROW + 2 * q) * 2);

    float acc[8][4];
    #pragma unroll
    for (int j = 0; j < 8; ++j)
        #pragma unroll
        for (int r = 0; r < 4; ++r) acc[j][r] = 0.0f;

    // First active scale tile per k16-step (6-sigma Ricker support, nested windows)
    const int jst[NSTEP] = {5,5,5,5, 4,4,4,4, 3,3,3, 2,2, 1, 0,0,0,0,0,0,
                            1, 2,2, 3,3,3, 4,4,4,4, 5,5,5,5};

    #pragma unroll
    for (int st = 0; st < NSTEP; ++st) {
        const int j0 = jst[st];
        const uint32_t xo = (uint32_t)(st * 32);
        const uint32_t a0 = lds32(xa + xo);
        const uint32_t a1 = lds32(xa + xo + 16);
        const uint32_t a3 = lds32(xa + xo + 32);
        #pragma unroll
        for (int j = j0; j < 8; ++j) {
            const uint32_t wa = wb0 + xo + (uint32_t)(j * (WROW * 8 * 2));
            const uint32_t b0 = lds32(wa);
            const uint32_t b1 = lds32(wa + 16);
            mma16816(acc[j], a0, a1, a1, a3, b0, b1);
        }
    }

    // ---- epilogue: transpose via smem, coalesced float4 stores ----
    __syncthreads();    // all warps done reading Wsm
    {
        const int tloc = 16 * wid + g;
        #pragma unroll
        for (int j = 0; j < 8; ++j) {
            const int s = 8 * j + 2 * q;
            Obuf[s * 140 + tloc]           = acc[j][0];
            Obuf[(s + 1) * 140 + tloc]     = acc[j][1];
            Obuf[s * 140 + tloc + 8]       = acc[j][2];
            Obuf[(s + 1) * 140 + tloc + 8] = acc[j][3];
        }
    }
    __syncthreads();
    {
        const size_t ob = ((size_t)(b * S_DIM)) * T_DIM + t0;
        for (int i = tid; i < 2048; i += 256) {
            const int s = i >> 5, tq = i & 31;
            float4 v = *reinterpret_cast<float4*>(&Obuf[s * 140 + 4 * tq]);
            *reinterpret_cast<float4*>(&out[ob + (size_t)s * T_DIM + 4 * tq]) = v;
        }
    }
}

extern "C" void kernel_launch(void* const* d_in, const int* in_sizes, int n_in,
                              void* d_out, int out_size) {
    const float* x = (const float*)d_in[0];   // [128, 4096]
    const float* W = (const float*)d_in[1];   // [64, 543]
    float* out = (float*)d_out;               // [128, 64, 4096]
    (void)in_sizes; (void)n_in; (void)out_size;

    prep_bank<<<(64 * WROW + 255) / 256, 256>>>(W);

    cudaFuncSetAttribute(cwt_mma_kernel,
                         cudaFuncAttributeMaxDynamicSharedMemorySize, SMEM_BYTES);
    dim3 grid(T_DIM / TT, 128);               // (32, 128) — 1 batch per CTA
    cwt_mma_kernel<<<grid, 256, SMEM_BYTES>>>(x, out);
}

// round 7
// speedup vs baseline: 3.3422x; 3.3422x over previous
#include <cuda_runtime.h>
#include <cuda_fp16.h>
#include <cstdint>

// out[b,s,t] = sum_k x[b, t+k-271] * W[s,k];  B=128, T=4096, S=64, K=543.
// fp16 mma.sync.m16n8k16 implicit GEMM, single pass, fp32 accumulate.
// 6-sigma Ricker support skip per scale tile; 2 batches per CTA (R5 config).

#define T_DIM   4096
#define S_DIM   64
#define K_DIM   543
#define NSTEP   34       // k16 steps over KPAD=544
#define WROW    552      // padded W row (conflict-free b-frag LDS)
#define TT      128      // t tile (M)
#define WIN     672      // x window: TT + 544
#define XROW    688      // padded x copy row (elems)

// smem: [0, 70656) W fp16 [64 s][552 kk]; then x fp16 [2 bb][2 copy][688]
#define WS_BYTES   (64 * WROW * 2)                     // 70656
#define X_OFF      WS_BYTES
#define SMEM_BYTES (WS_BYTES + 2 * 2 * XROW * 2)       // 76160

__device__ uint16_t g_W[64][WROW];     // fp16, zero-padded

__global__ void prep_bank(const float* __restrict__ W) {
    int idx = blockIdx.x * blockDim.x + threadIdx.x;
    if (idx >= 64 * WROW) return;
    int s  = idx / WROW;
    int kk = idx % WROW;
    float w = (kk < K_DIM) ? W[s * K_DIM + kk] : 0.0f;
    __half h = __float2half_rn(w);
    g_W[s][kk] = *reinterpret_cast<uint16_t*>(&h);
}

__device__ __forceinline__ uint32_t smem_u32(const void* p) {
    uint32_t a;
    asm("{ .reg .u64 t; cvta.to.shared.u64 t, %1; cvt.u32.u64 %0, t; }" : "=r"(a) : "l"(p));
    return a;
}
__device__ __forceinline__ uint32_t lds32(uint32_t a) {
    uint32_t v; asm volatile("ld.shared.b32 %0, [%1];" : "=r"(v) : "r"(a)); return v;
}
__device__ __forceinline__ void mma16816(float* c, uint32_t a0, uint32_t a1,
                                         uint32_t a2, uint32_t a3,
                                         uint32_t b0, uint32_t b1) {
    asm volatile(
        "mma.sync.aligned.m16n8k16.row.col.f32.f16.f16.f32 "
        "{%0,%1,%2,%3}, {%4,%5,%6,%7}, {%8,%9}, {%0,%1,%2,%3};"
        : "+f"(c[0]), "+f"(c[1]), "+f"(c[2]), "+f"(c[3])
        : "r"(a0), "r"(a1), "r"(a2), "r"(a3), "r"(b0), "r"(b1));
}

extern __shared__ char smem_raw[];

__global__ __launch_bounds__(256, 2)
void cwt_mma_kernel(const float* __restrict__ x, float* __restrict__ out) {
    uint16_t* Wsm  = reinterpret_cast<uint16_t*>(smem_raw);
    uint16_t* Xsm  = reinterpret_cast<uint16_t*>(smem_raw + X_OFF);
    float*    Obuf = reinterpret_cast<float*>(smem_raw);   // epilogue reuse

    const int tid  = threadIdx.x;
    const int wid  = tid >> 5;
    const int lane = tid & 31;
    const int t0   = blockIdx.x * TT;
    const int bp   = blockIdx.y;          // batch pair

    // ---- stage W (entire padded bank, fp16) ----
    {
        const int4* src = reinterpret_cast<const int4*>(&g_W[0][0]);
        int4* dst = reinterpret_cast<int4*>(Wsm);
        for (int i = tid; i < WS_BYTES / 16; i += 256) dst[i] = src[i];
    }
    // ---- stage x windows (fp16 + 1-elem-shifted copies) ----
    for (int bb = 0; bb < 2; ++bb) {
        const float* xr = x + (size_t)(bp * 2 + bb) * T_DIM;
        uint16_t* p = Xsm + bb * 2 * XROW;
        for (int i = tid; i < WIN; i += 256) {
            int g = t0 + i - 271;
            float v = (g >= 0 && g < T_DIM) ? xr[g] : 0.0f;
            __half h = __float2half_rn(v);
            uint16_t hb = *reinterpret_cast<uint16_t*>(&h);
            p[i] = hb;
            if (i) p[XROW + i - 1] = hb;
        }
    }
    __syncthreads();

    // ---- fragment addresses ----
    const int g    = lane >> 2;
    const int q    = lane & 3;
    const int podd = g & 1;
    const int eb   = 16 * wid + g + 2 * q - podd;
    uint32_t xa[2];
    #pragma unroll
    for (int bb = 0; bb < 2; ++bb)
        xa[bb] = smem_u32(Xsm) + (uint32_t)(((bb * 2 + podd) * XROW + eb) * 2);
    const uint32_t wb0 = smem_u32(Wsm) + (uint32_t)((g * WROW + 2 * q) * 2);

    float acc[2][8][4];
    #pragma unroll
    for (int bb = 0; bb < 2; ++bb)
        #pragma unroll
        for (int j = 0; j < 8; ++j)
            #pragma unroll
            for (int r = 0; r < 4; ++r) acc[bb][j][r] = 0.0f;

    // First active scale tile per k16-step (6-sigma Ricker support, nested)
    const int jst[NSTEP] = {5,5,5,5, 4,4,4,4, 3,3,3, 2,2, 1, 0,0,0,0,0,0,
                            1, 2,2, 3,3,3, 4,4,4,4, 5,5,5,5};

    #pragma unroll 2
    for (int st = 0; st < NSTEP; ++st) {
        const int j0 = jst[st];
        const uint32_t xo = (uint32_t)(st * 32);
        uint32_t wf[8][2];
        #pragma unroll
        for (int j = 0; j < 8; ++j) {
            if (j < j0) continue;
            const uint32_t wa = wb0 + xo + (uint32_t)(j * (WROW * 8 * 2));
            wf[j][0] = lds32(wa);
            wf[j][1] = lds32(wa + 16);
        }
        #pragma unroll
        for (int bb = 0; bb < 2; ++bb) {
            const uint32_t bh = xa[bb] + xo;
            const uint32_t a0 = lds32(bh);
            const uint32_t a1 = lds32(bh + 16);
            const uint32_t a3 = lds32(bh + 32);
            #pragma unroll
            for (int j = 0; j < 8; ++j) {
                if (j < j0) continue;
                mma16816(acc[bb][j], a0, a1, a1, a3, wf[j][0], wf[j][1]);
            }
        }
    }

    // ---- epilogue: transpose via smem, coalesced float4 stores ----
    for (int bb = 0; bb < 2; ++bb) {
        __syncthreads();
        const int tloc = 16 * wid + g;
        #pragma unroll
        for (int j = 0; j < 8; ++j) {
            const int s = 8 * j + 2 * q;
            Obuf[s * 140 + tloc]           = acc[bb][j][0];
            Obuf[(s + 1) * 140 + tloc]     = acc[bb][j][1];
            Obuf[s * 140 + tloc + 8]       = acc[bb][j][2];
            Obuf[(s + 1) * 140 + tloc + 8] = acc[bb][j][3];
        }
        __syncthreads();
        const size_t ob = ((size_t)((bp * 2 + bb) * S_DIM)) * T_DIM + t0;
        for (int i = tid; i < 2048; i += 256) {
            const int s = i >> 5, tq = i & 31;
            float4 v = *reinterpret_cast<float4*>(&Obuf[s * 140 + 4 * tq]);
            *reinterpret_cast<float4*>(&out[ob + (size_t)s * T_DIM + 4 * tq]) = v;
        }
    }
}

extern "C" void kernel_launch(void* const* d_in, const int* in_sizes, int n_in,
                              void* d_out, int out_size) {
    const float* x = (const float*)d_in[0];   // [128, 4096]
    const float* W = (const float*)d_in[1];   // [64, 543]
    float* out = (float*)d_out;               // [128, 64, 4096]
    (void)in_sizes; (void)n_in; (void)out_size;

    prep_bank<<<(64 * WROW + 255) / 256, 256>>>(W);

    cudaFuncSetAttribute(cwt_mma_kernel,
                         cudaFuncAttributeMaxDynamicSharedMemorySize, SMEM_BYTES);
    dim3 grid(T_DIM / TT, 64);                // 2 batches per CTA
    cwt_mma_kernel<<<grid, 256, SMEM_BYTES>>>(x, out);
}

// round 8
// speedup vs baseline: 4.7192x; 1.4120x over previous
#include <cuda_runtime.h>
#include <cuda_fp16.h>
#include <cstdint>

// out[b,s,t] = sum_k x[b, t+k-271] * W[s,k];  B=128, T=4096, S=64, K=543.
// fp16 mma.sync.m16n8k16 implicit GEMM, single pass, fp32 accumulate.
// Fully-unrolled k-loop with compile-time 6-sigma Ricker support skip.

#define T_DIM   4096
#define S_DIM   64
#define K_DIM   543
#define NSTEP   34
#define WROW    552
#define TT      128
#define WIN     672
#define XROW    688

#define WS_BYTES   (64 * WROW * 2)                     // 70656
#define X_OFF      WS_BYTES
#define SMEM_BYTES (WS_BYTES + 2 * 2 * XROW * 2)       // 76160

__device__ uint16_t g_W[64][WROW];

__global__ void prep_bank(const float* __restrict__ W) {
    int idx = blockIdx.x * blockDim.x + threadIdx.x;
    if (idx >= 64 * WROW) return;
    int s  = idx / WROW;
    int kk = idx % WROW;
    float w = (kk < K_DIM) ? W[s * K_DIM + kk] : 0.0f;
    __half h = __float2half_rn(w);
    g_W[s][kk] = *reinterpret_cast<uint16_t*>(&h);
}

__device__ __forceinline__ uint32_t smem_u32(const void* p) {
    uint32_t a;
    asm("{ .reg .u64 t; cvta.to.shared.u64 t, %1; cvt.u32.u64 %0, t; }" : "=r"(a) : "l"(p));
    return a;
}
__device__ __forceinline__ uint32_t lds32(uint32_t a) {
    uint32_t v; asm volatile("ld.shared.b32 %0, [%1];" : "=r"(v) : "r"(a)); return v;
}
__device__ __forceinline__ void mma16816(float* c, uint32_t a0, uint32_t a1,
                                         uint32_t a2, uint32_t a3,
                                         uint32_t b0, uint32_t b1) {
    asm volatile(
        "mma.sync.aligned.m16n8k16.row.col.f32.f16.f16.f32 "
        "{%0,%1,%2,%3}, {%4,%5,%6,%7}, {%8,%9}, {%0,%1,%2,%3};"
        : "+f"(c[0]), "+f"(c[1]), "+f"(c[2]), "+f"(c[3])
        : "r"(a0), "r"(a1), "r"(a2), "r"(a3), "r"(b0), "r"(b1));
}

// Compile-time first-active-scale-tile per k16-step (6-sigma Ricker support).
__device__ __forceinline__ constexpr int jstart(int st) {
    constexpr int tab[NSTEP] = {5,5,5,5, 4,4,4,4, 3,3,3, 2,2, 1, 0,0,0,0,0,0,
                                1, 2,2, 3,3,3, 4,4,4,4, 5,5,5,5};
    return tab[st];
}

extern __shared__ char smem_raw[];

__global__ __launch_bounds__(256, 2)
void cwt_mma_kernel(const float* __restrict__ x, float* __restrict__ out) {
    uint16_t* Wsm  = reinterpret_cast<uint16_t*>(smem_raw);
    uint16_t* Xsm  = reinterpret_cast<uint16_t*>(smem_raw + X_OFF);
    float*    Obuf = reinterpret_cast<float*>(smem_raw);

    const int tid  = threadIdx.x;
    const int wid  = tid >> 5;
    const int lane = tid & 31;
    const int t0   = blockIdx.x * TT;
    const int bp   = blockIdx.y;

    // ---- stage W ----
    {
        const int4* src = reinterpret_cast<const int4*>(&g_W[0][0]);
        int4* dst = reinterpret_cast<int4*>(Wsm);
        for (int i = tid; i < WS_BYTES / 16; i += 256) dst[i] = src[i];
    }
    // ---- stage x windows (fp16 + shifted copies) ----
    for (int bb = 0; bb < 2; ++bb) {
        const float* xr = x + (size_t)(bp * 2 + bb) * T_DIM;
        uint16_t* p = Xsm + bb * 2 * XROW;
        for (int i = tid; i < WIN; i += 256) {
            int g = t0 + i - 271;
            float v = (g >= 0 && g < T_DIM) ? xr[g] : 0.0f;
            __half h = __float2half_rn(v);
            uint16_t hb = *reinterpret_cast<uint16_t*>(&h);
            p[i] = hb;
            if (i) p[XROW + i - 1] = hb;
        }
    }
    __syncthreads();

    const int g    = lane >> 2;
    const int q    = lane & 3;
    const int podd = g & 1;
    const int eb   = 16 * wid + g + 2 * q - podd;
    uint32_t xa[2];
    #pragma unroll
    for (int bb = 0; bb < 2; ++bb)
        xa[bb] = smem_u32(Xsm) + (uint32_t)(((bb * 2 + podd) * XROW + eb) * 2);
    const uint32_t wb0 = smem_u32(Wsm) + (uint32_t)((g * WROW + 2 * q) * 2);

    float acc[2][8][4];
    #pragma unroll
    for (int bb = 0; bb < 2; ++bb)
        #pragma unroll
        for (int j = 0; j < 8; ++j)
            #pragma unroll
            for (int r = 0; r < 4; ++r) acc[bb][j][r] = 0.0f;

    #pragma unroll
    for (int st = 0; st < NSTEP; ++st) {
        const int j0 = jstart(st);          // compile-time under full unroll
        const uint32_t xo = (uint32_t)(st * 32);
        uint32_t wf[8][2];
        #pragma unroll
        for (int j = 0; j < 8; ++j) {
            if (j < j0) continue;           // compile-time dead-code elim
            const uint32_t wa = wb0 + xo + (uint32_t)(j * (WROW * 8 * 2));
            wf[j][0] = lds32(wa);
            wf[j][1] = lds32(wa + 16);
        }
        #pragma unroll
        for (int bb = 0; bb < 2; ++bb) {
            const uint32_t bh = xa[bb] + xo;
            const uint32_t a0 = lds32(bh);
            const uint32_t a1 = lds32(bh + 16);
            const uint32_t a3 = lds32(bh + 32);
            #pragma unroll
            for (int j = 0; j < 8; ++j) {
                if (j < j0) continue;
                mma16816(acc[bb][j], a0, a1, a1, a3, wf[j][0], wf[j][1]);
            }
        }
    }

    // ---- epilogue ----
    for (int bb = 0; bb < 2; ++bb) {
        __syncthreads();
        const int tloc = 16 * wid + g;
        #pragma unroll
        for (int j = 0; j < 8; ++j) {
            const int s = 8 * j + 2 * q;
            Obuf[s * 140 + tloc]           = acc[bb][j][0];
            Obuf[(s + 1) * 140 + tloc]     = acc[bb][j][1];
            Obuf[s * 140 + tloc + 8]       = acc[bb][j][2];
            Obuf[(s + 1) * 140 + tloc + 8] = acc[bb][j][3];
        }
        __syncthreads();
        const size_t ob = ((size_t)((bp * 2 + bb) * S_DIM)) * T_DIM + t0;
        for (int i = tid; i < 2048; i += 256) {
            const int s = i >> 5, tq = i & 31;
            float4 v = *reinterpret_cast<float4*>(&Obuf[s * 140 + 4 * tq]);
            *reinterpret_cast<float4*>(&out[ob + (size_t)s * T_DIM + 4 * tq]) = v;
        }
    }
}

extern "C" void kernel_launch(void* const* d_in, const int* in_sizes, int n_in,
                              void* d_out, int out_size) {
    const float* x = (const float*)d_in[0];   // [128, 4096]
    const float* W = (const float*)d_in[1];   // [64, 543]
    float* out = (float*)d_out;               // [128, 64, 4096]
    (void)in_sizes; (void)n_in; (void)out_size;

    prep_bank<<<(64 * WROW + 255) / 256, 256>>>(W);

    cudaFuncSetAttribute(cwt_mma_kernel,
                         cudaFuncAttributeMaxDynamicSharedMemorySize, SMEM_BYTES);
    dim3 grid(T_DIM / TT, 64);                // 2 batches per CTA
    cwt_mma_kernel<<<grid, 256, SMEM_BYTES>>>(x, out);
}

// round 9
// speedup vs baseline: 4.8467x; 1.0270x over previous
#include <cuda_runtime.h>
#include <cuda_fp16.h>
#include <cstdint>

// out[b,s,t] = sum_k x[b, t+k-271] * W[s,k];  B=128, T=4096, S=64, K=543.
// fp16 mma.sync.m16n8k16 implicit GEMM, fp32 accumulate, compile-time
// 6-sigma support skip. Persistent CTAs: W staged once, direct gmem stores.

#define T_DIM   4096
#define S_DIM   64
#define K_DIM   543
#define NSTEP   34
#define WROW    552
#define TT      128
#define WIN     672
#define XROW    688

#define NCTA    296            // 2 CTAs/SM * 148 SMs
#define NTILE   2048           // 32 t-tiles * 64 batch-pairs
#define MAXIT   7              // ceil(2048/296)

#define WS_BYTES   (64 * WROW * 2)                     // 70656
#define X_OFF      WS_BYTES
#define SMEM_BYTES (WS_BYTES + 2 * 2 * XROW * 2)       // 76160

__device__ uint16_t g_W[64][WROW];

__global__ void prep_bank(const float* __restrict__ W) {
    int idx = blockIdx.x * blockDim.x + threadIdx.x;
    if (idx >= 64 * WROW) return;
    int s  = idx / WROW;
    int kk = idx % WROW;
    float w = (kk < K_DIM) ? W[s * K_DIM + kk] : 0.0f;
    __half h = __float2half_rn(w);
    g_W[s][kk] = *reinterpret_cast<uint16_t*>(&h);
}

__device__ __forceinline__ uint32_t smem_u32(const void* p) {
    uint32_t a;
    asm("{ .reg .u64 t; cvta.to.shared.u64 t, %1; cvt.u32.u64 %0, t; }" : "=r"(a) : "l"(p));
    return a;
}
__device__ __forceinline__ uint32_t lds32(uint32_t a) {
    uint32_t v; asm volatile("ld.shared.b32 %0, [%1];" : "=r"(v) : "r"(a)); return v;
}
__device__ __forceinline__ void mma16816(float* c, uint32_t a0, uint32_t a1,
                                         uint32_t a2, uint32_t a3,
                                         uint32_t b0, uint32_t b1) {
    asm volatile(
        "mma.sync.aligned.m16n8k16.row.col.f32.f16.f16.f32 "
        "{%0,%1,%2,%3}, {%4,%5,%6,%7}, {%8,%9}, {%0,%1,%2,%3};"
        : "+f"(c[0]), "+f"(c[1]), "+f"(c[2]), "+f"(c[3])
        : "r"(a0), "r"(a1), "r"(a2), "r"(a3), "r"(b0), "r"(b1));
}

// First active scale tile per k16-step (6-sigma Ricker support).
__device__ __forceinline__ constexpr int jstart(int st) {
    constexpr int tab[NSTEP] = {5,5,5,5, 4,4,4,4, 3,3,3, 2,2, 1, 0,0,0,0,0,0,
                                1, 2,2, 3,3,3, 4,4,4,4, 5,5,5,5};
    return tab[st];
}

extern __shared__ char smem_raw[];

__global__ __launch_bounds__(256, 2)
void cwt_mma_kernel(const float* __restrict__ x, float* __restrict__ out) {
    uint16_t* Wsm = reinterpret_cast<uint16_t*>(smem_raw);
    uint16_t* Xsm = reinterpret_cast<uint16_t*>(smem_raw + X_OFF);

    const int tid  = threadIdx.x;
    const int wid  = tid >> 5;
    const int lane = tid & 31;

    // ---- stage W once per CTA ----
    {
        const int4* src = reinterpret_cast<const int4*>(&g_W[0][0]);
        int4* dst = reinterpret_cast<int4*>(Wsm);
        for (int i = tid; i < WS_BYTES / 16; i += 256) dst[i] = src[i];
    }

    // ---- tile-invariant fragment addresses ----
    const int g    = lane >> 2;
    const int q    = lane & 3;
    const int podd = g & 1;
    const int eb   = 16 * wid + g + 2 * q - podd;
    uint32_t xa[2];
    #pragma unroll
    for (int bb = 0; bb < 2; ++bb)
        xa[bb] = smem_u32(Xsm) + (uint32_t)(((bb * 2 + podd) * XROW + eb) * 2);
    const uint32_t wb0 = smem_u32(Wsm) + (uint32_t)((g * WROW + 2 * q) * 2);

    for (int it = 0; it < MAXIT; ++it) {
        const int tile = blockIdx.x + NCTA * it;    // uniform per CTA
        if (tile >= NTILE) break;
        const int bp = tile >> 5;
        const int t0 = (tile & 31) << 7;

        __syncthreads();     // prior tile's compute done reading Xsm
        // ---- stage x windows (fp16 + 1-elem-shifted copies) ----
        #pragma unroll
        for (int bb = 0; bb < 2; ++bb) {
            const float* xr = x + (size_t)(bp * 2 + bb) * T_DIM;
            uint16_t* p = Xsm + bb * 2 * XROW;
            for (int i = tid; i < WIN; i += 256) {
                int gg = t0 + i - 271;
                float v = (gg >= 0 && gg < T_DIM) ? xr[gg] : 0.0f;
                __half h = __float2half_rn(v);
                uint16_t hb = *reinterpret_cast<uint16_t*>(&h);
                p[i] = hb;
                if (i) p[XROW + i - 1] = hb;
            }
        }
        __syncthreads();

        float acc[2][8][4];
        #pragma unroll
        for (int bb = 0; bb < 2; ++bb)
            #pragma unroll
            for (int j = 0; j < 8; ++j)
                #pragma unroll
                for (int r = 0; r < 4; ++r) acc[bb][j][r] = 0.0f;

        #pragma unroll
        for (int st = 0; st < NSTEP; ++st) {
            const int j0 = jstart(st);              // compile-time
            const uint32_t xo = (uint32_t)(st * 32);
            uint32_t wf[8][2];
            #pragma unroll
            for (int j = 0; j < 8; ++j) {
                if (j < j0) continue;
                const uint32_t wa = wb0 + xo + (uint32_t)(j * (WROW * 8 * 2));
                wf[j][0] = lds32(wa);
                wf[j][1] = lds32(wa + 16);
            }
            #pragma unroll
            for (int bb = 0; bb < 2; ++bb) {
                const uint32_t bh = xa[bb] + xo;
                const uint32_t a0 = lds32(bh);
                const uint32_t a1 = lds32(bh + 16);
                const uint32_t a3 = lds32(bh + 32);
                #pragma unroll
                for (int j = 0; j < 8; ++j) {
                    if (j < j0) continue;
                    mma16816(acc[bb][j], a0, a1, a1, a3, wf[j][0], wf[j][1]);
                }
            }
        }

        // ---- direct global stores (full 32B-sector coverage per quarter-warp) ----
        const int tg = t0 + 16 * wid + g;
        #pragma unroll
        for (int bb = 0; bb < 2; ++bb) {
            float* ob = out + ((size_t)((bp * 2 + bb) * S_DIM)) * T_DIM;
            #pragma unroll
            for (int j = 0; j < 8; ++j) {
                float* r0 = ob + (size_t)(8 * j + 2 * q) * T_DIM + tg;
                float* r1 = r0 + T_DIM;
                r0[0] = acc[bb][j][0];
                r1[0] = acc[bb][j][1];
                r0[8] = acc[bb][j][2];
                r1[8] = acc[bb][j][3];
            }
        }
    }
}

extern "C" void kernel_launch(void* const* d_in, const int* in_sizes, int n_in,
                              void* d_out, int out_size) {
    const float* x = (const float*)d_in[0];   // [128, 4096]
    const float* W = (const float*)d_in[1];   // [64, 543]
    float* out = (float*)d_out;               // [128, 64, 4096]
    (void)in_sizes; (void)n_in; (void)out_size;

    prep_bank<<<(64 * WROW + 255) / 256, 256>>>(W);

    cudaFuncSetAttribute(cwt_mma_kernel,
                         cudaFuncAttributeMaxDynamicSharedMemorySize, SMEM_BYTES);
    cwt_mma_kernel<<<NCTA, 256, SMEM_BYTES>>>(x, out);
}

// round 10
// speedup vs baseline: 5.5330x; 1.1416x over previous
#include <cuda_runtime.h>
#include <cuda_fp16.h>
#include <cstdint>

// out[b,s,t] = sum_k x[b, t+k-271] * W[s,k];  B=128, T=4096, S=64, K=543.
// fp16 mma.sync.m16n8k16 implicit GEMM, fp32 accum, compile-time 6-sigma skip.
// Persistent CTAs + double-buffered x windows (prefetch, 1 sync per tile).

#define T_DIM   4096
#define S_DIM   64
#define K_DIM   543
#define NSTEP   34
#define WROW    552
#define TT      128
#define WIN     672
#define XROW    688

#define NCTA    296
#define NTILE   2048
#define MAXIT   7

#define WS_BYTES   (64 * WROW * 2)                       // 70656
#define X_OFF      WS_BYTES
#define XBUF_E     (2 * 2 * XROW)                        // elems per buffer
#define SMEM_BYTES (WS_BYTES + 2 * XBUF_E * 2)           // 81664

__device__ uint16_t g_W[64][WROW];

__global__ void prep_bank(const float* __restrict__ W) {
    int idx = blockIdx.x * blockDim.x + threadIdx.x;
    if (idx >= 64 * WROW) return;
    int s  = idx / WROW;
    int kk = idx % WROW;
    float w = (kk < K_DIM) ? W[s * K_DIM + kk] : 0.0f;
    __half h = __float2half_rn(w);
    g_W[s][kk] = *reinterpret_cast<uint16_t*>(&h);
}

__device__ __forceinline__ uint32_t smem_u32(const void* p) {
    uint32_t a;
    asm("{ .reg .u64 t; cvta.to.shared.u64 t, %1; cvt.u32.u64 %0, t; }" : "=r"(a) : "l"(p));
    return a;
}
__device__ __forceinline__ uint32_t lds32(uint32_t a) {
    uint32_t v; asm volatile("ld.shared.b32 %0, [%1];" : "=r"(v) : "r"(a)); return v;
}
__device__ __forceinline__ void mma16816(float* c, uint32_t a0, uint32_t a1,
                                         uint32_t a2, uint32_t a3,
                                         uint32_t b0, uint32_t b1) {
    asm volatile(
        "mma.sync.aligned.m16n8k16.row.col.f32.f16.f16.f32 "
        "{%0,%1,%2,%3}, {%4,%5,%6,%7}, {%8,%9}, {%0,%1,%2,%3};"
        : "+f"(c[0]), "+f"(c[1]), "+f"(c[2]), "+f"(c[3])
        : "r"(a0), "r"(a1), "r"(a2), "r"(a3), "r"(b0), "r"(b1));
}

__device__ __forceinline__ constexpr int jstart(int st) {
    constexpr int tab[NSTEP] = {5,5,5,5, 4,4,4,4, 3,3,3, 2,2, 1, 0,0,0,0,0,0,
                                1, 2,2, 3,3,3, 4,4,4,4, 5,5,5,5};
    return tab[st];
}

extern __shared__ char smem_raw[];

__global__ __launch_bounds__(256, 2)
void cwt_mma_kernel(const float* __restrict__ x, float* __restrict__ out) {
    uint16_t* Wsm = reinterpret_cast<uint16_t*>(smem_raw);
    uint16_t* Xsm = reinterpret_cast<uint16_t*>(smem_raw + X_OFF);

    const int tid  = threadIdx.x;
    const int wid  = tid >> 5;
    const int lane = tid & 31;

    // ---- stage W once per CTA ----
    {
        const int4* src = reinterpret_cast<const int4*>(&g_W[0][0]);
        int4* dst = reinterpret_cast<int4*>(Wsm);
        for (int i = tid; i < WS_BYTES / 16; i += 256) dst[i] = src[i];
    }

    // ---- fragment address constants ----
    const int g    = lane >> 2;
    const int q    = lane & 3;
    const int podd = g & 1;
    const int eb   = 16 * wid + g + 2 * q - podd;
    // xa[buf][bb]
    uint32_t xa[2][2];
    #pragma unroll
    for (int bf = 0; bf < 2; ++bf)
        #pragma unroll
        for (int bb = 0; bb < 2; ++bb)
            xa[bf][bb] = smem_u32(Xsm) +
                (uint32_t)((((bf * 2 + bb) * 2 + podd) * XROW + eb) * 2);
    const uint32_t wb0 = smem_u32(Wsm) + (uint32_t)((g * WROW + 2 * q) * 2);

    // ---- prologue: prefetch + stage tile 0 into buffer 0 ----
    float pre[2][3];
    {
        const int tile = blockIdx.x;
        const int bp = tile >> 5, t0 = (tile & 31) << 7;
        #pragma unroll
        for (int bb = 0; bb < 2; ++bb) {
            const float* xr = x + (size_t)(bp * 2 + bb) * T_DIM;
            #pragma unroll
            for (int r = 0; r < 3; ++r) {
                int i = tid + 256 * r;
                int gg = t0 + i - 271;
                pre[bb][r] = (i < WIN && gg >= 0 && gg < T_DIM) ? xr[gg] : 0.0f;
            }
        }
        #pragma unroll
        for (int bb = 0; bb < 2; ++bb) {
            uint16_t* p = Xsm + bb * 2 * XROW;   // buffer 0
            #pragma unroll
            for (int r = 0; r < 3; ++r) {
                int i = tid + 256 * r;
                if (i < WIN) {
                    __half h = __float2half_rn(pre[bb][r]);
                    uint16_t hb = *reinterpret_cast<uint16_t*>(&h);
                    p[i] = hb;
                    if (i) p[XROW + i - 1] = hb;
                }
            }
        }
    }
    __syncthreads();

    for (int it = 0; it < MAXIT; ++it) {
        const int tile = blockIdx.x + NCTA * it;
        if (tile >= NTILE) break;
        const int bp = tile >> 5;
        const int t0 = (tile & 31) << 7;
        const int ntile = tile + NCTA;
        const bool have_next = (ntile < NTILE);

        // ---- prefetch next tile's x (latency hidden under compute) ----
        if (have_next) {
            const int nbp = ntile >> 5, nt0 = (ntile & 31) << 7;
            #pragma unroll
            for (int bb = 0; bb < 2; ++bb) {
                const float* xr = x + (size_t)(nbp * 2 + bb) * T_DIM;
                #pragma unroll
                for (int r = 0; r < 3; ++r) {
                    int i = tid + 256 * r;
                    int gg = nt0 + i - 271;
                    pre[bb][r] = (i < WIN && gg >= 0 && gg < T_DIM) ? xr[gg] : 0.0f;
                }
            }
        }

        // ---- compute from buffer it&1 ----
        const uint32_t xc0 = (it & 1) ? xa[1][0] : xa[0][0];
        const uint32_t xc1 = (it & 1) ? xa[1][1] : xa[0][1];

        float acc[2][8][4];
        #pragma unroll
        for (int bb = 0; bb < 2; ++bb)
            #pragma unroll
            for (int j = 0; j < 8; ++j)
                #pragma unroll
                for (int r = 0; r < 4; ++r) acc[bb][j][r] = 0.0f;

        #pragma unroll
        for (int st = 0; st < NSTEP; ++st) {
            const int j0 = jstart(st);
            const uint32_t xo = (uint32_t)(st * 32);
            uint32_t wf[8][2];
            #pragma unroll
            for (int j = 0; j < 8; ++j) {
                if (j < j0) continue;
                const uint32_t wa = wb0 + xo + (uint32_t)(j * (WROW * 8 * 2));
                wf[j][0] = lds32(wa);
                wf[j][1] = lds32(wa + 16);
            }
            #pragma unroll
            for (int bb = 0; bb < 2; ++bb) {
                const uint32_t bh = (bb ? xc1 : xc0) + xo;
                const uint32_t a0 = lds32(bh);
                const uint32_t a1 = lds32(bh + 16);
                const uint32_t a3 = lds32(bh + 32);
                #pragma unroll
                for (int j = 0; j < 8; ++j) {
                    if (j < j0) continue;
                    mma16816(acc[bb][j], a0, a1, a1, a3, wf[j][0], wf[j][1]);
                }
            }
        }

        // ---- output stores ----
        const int tg = t0 + 16 * wid + g;
        #pragma unroll
        for (int bb = 0; bb < 2; ++bb) {
            float* ob = out + ((size_t)((bp * 2 + bb) * S_DIM)) * T_DIM;
            #pragma unroll
            for (int j = 0; j < 8; ++j) {
                float* r0 = ob + (size_t)(8 * j + 2 * q) * T_DIM + tg;
                float* r1 = r0 + T_DIM;
                r0[0] = acc[bb][j][0];
                r1[0] = acc[bb][j][1];
                r0[8] = acc[bb][j][2];
                r1[8] = acc[bb][j][3];
            }
        }

        // ---- stage next tile into buffer (it+1)&1, one sync ----
        if (have_next) {
            uint16_t* base = Xsm + ((it + 1) & 1) * XBUF_E;
            #pragma unroll
            for (int bb = 0; bb < 2; ++bb) {
                uint16_t* p = base + bb * 2 * XROW;
                #pragma unroll
                for (int r = 0; r < 3; ++r) {
                    int i = tid + 256 * r;
                    if (i < WIN) {
                        __half h = __float2half_rn(pre[bb][r]);
                        uint16_t hb = *reinterpret_cast<uint16_t*>(&h);
                        p[i] = hb;
                        if (i) p[XROW + i - 1] = hb;
                    }
                }
            }
            __syncthreads();
        }
    }
}

extern "C" void kernel_launch(void* const* d_in, const int* in_sizes, int n_in,
                              void* d_out, int out_size) {
    const float* x = (const float*)d_in[0];   // [128, 4096]
    const float* W = (const float*)d_in[1];   // [64, 543]
    float* out = (float*)d_out;               // [128, 64, 4096]
    (void)in_sizes; (void)n_in; (void)out_size;

    prep_bank<<<(64 * WROW + 255) / 256, 256>>>(W);

    cudaFuncSetAttribute(cwt_mma_kernel,
                         cudaFuncAttributeMaxDynamicSharedMemorySize, SMEM_BYTES);
    cwt_mma_kernel<<<NCTA, 256, SMEM_BYTES>>>(x, out);
}